// round 11
// baseline (speedup 1.0000x reference)
#include <cuda_runtime.h>
#include <cuda_bf16.h>
#include <mma.h>

using namespace nvcuda;

// ---------------------------------------------------------------------------
// NeuralODEFlow: z' = mlp(z), Euler, log_det via finite-difference trace.
// Key identity (mlp is piecewise linear in z):
//   trace_step = dt/H * (Sy_new - Sy_old)   [the "updated-z bug" term, Sy = sum_j y_j]
//              + dt * m1^T Q m2             [exact masked Jacobian trace]
// with Q[k,i] = W2[k,i] * (W3@W1)[i,k], m1/m2 = ReLU masks at z_new.
//
// R10: V = m1@Q moved to bf16 wmma tensor cores (huge tolerance: bilinear term
// is ~1e-4 of log_det). y never materialized: k2 epilogue emits per-cb rowsums,
// k1 Euler-updates z from ypart directly, k3 is a 4-CTA scalar update.
// ---------------------------------------------------------------------------

#define BATCH 1024
#define DIM   64
#define HID   512
#define NSTEP 9
#define HSTEP 1e-5f

// scratch (device globals: allocation-free)
__device__ float         g_Q [HID * HID];
__device__ __nv_bfloat16 g_Qb[HID * HID];
__device__ float g_z[BATCH * DIM];
__device__ float g_h1[BATCH * HID];
__device__ float g_ypart[BATCH * 8 * DIM];   // [row][cb][j]
__device__ float g_part [BATCH * 8];         // bilinear partials
__device__ float g_ysump[BATCH * 8];         // rowsum-of-y partials (excl. b3)
__device__ float g_ysum[2][BATCH];           // ping-pong Sy per eval

// ---------------------------------------------------------------------------
// k_init: Q[k,i] = W2[k,i] * P[i,k], P = W3 @ W1 ; also bf16 copy, zero logdet.
// grid (8,8), 256 thr.
// ---------------------------------------------------------------------------
__global__ __launch_bounds__(256) void k_init(const float* __restrict__ W1,
                                              const float* __restrict__ W2,
                                              const float* __restrict__ W3,
                                              float* __restrict__ out_logdet) {
    __shared__ float w3t[64][68];   // w3t[j][i] = W3[i0+i][j]
    __shared__ float w1s[64][64];   // w1s[j][k] = W1[j][k0+k]
    int i0 = blockIdx.x * 64, k0 = blockIdx.y * 64;
    int t = threadIdx.x;

#pragma unroll
    for (int q = 0; q < 16; ++q) {
        int e = t + 256 * q;
        int hi = e >> 6, lo = e & 63;
        w3t[lo][hi] = W3[(i0 + hi) * DIM + lo];
        w1s[hi][lo] = W1[hi * HID + k0 + lo];
    }
    __syncthreads();

    int tx = t & 15, ty = t >> 4;
    float acc[4][4];
#pragma unroll
    for (int r = 0; r < 4; ++r)
#pragma unroll
        for (int c = 0; c < 4; ++c) acc[r][c] = 0.f;

#pragma unroll 4
    for (int j = 0; j < 64; ++j) {
        float a[4], b[4];
        *(float4*)a = *(const float4*)&w3t[j][tx * 4];
        *(float4*)b = *(const float4*)&w1s[j][ty * 4];
#pragma unroll
        for (int r = 0; r < 4; ++r)
#pragma unroll
            for (int c = 0; c < 4; ++c) acc[r][c] += b[r] * a[c];
    }

#pragma unroll
    for (int r = 0; r < 4; ++r) {
        int idx = (k0 + ty * 4 + r) * HID + i0 + tx * 4;
        float4 w2v = *(const float4*)&W2[idx];
        float4 qv;
        qv.x = w2v.x * acc[r][0];
        qv.y = w2v.y * acc[r][1];
        qv.z = w2v.z * acc[r][2];
        qv.w = w2v.w * acc[r][3];
        *(float4*)&g_Q[idx] = qv;
        __nv_bfloat162 q01 = __floats2bfloat162_rn(qv.x, qv.y);
        __nv_bfloat162 q23 = __floats2bfloat162_rn(qv.z, qv.w);
        *(__nv_bfloat162*)&g_Qb[idx]     = q01;
        *(__nv_bfloat162*)&g_Qb[idx + 2] = q23;
    }

    if (blockIdx.x == 0 && blockIdx.y == 0) {
        for (int i = t; i < BATCH; i += 256) out_logdet[i] = 0.f;
    }
}

// ---------------------------------------------------------------------------
// K1: z_new = (first ? x : z + dt*(sum_cb ypart + b3));  h1 = relu(z_new@W1+b1)
// grid: 128 blocks * 256 threads, 8 rows per block.
// ---------------------------------------------------------------------------
__global__ __launch_bounds__(256) void k1_layer1(const float* __restrict__ xin,
                                                 const float* __restrict__ W1,
                                                 const float* __restrict__ b1,
                                                 const float* __restrict__ b3,
                                                 float dt, int first) {
    __shared__ float zs[8 * 64];
    int row0 = blockIdx.x * 8;
    int t = threadIdx.x;

#pragma unroll
    for (int q = 0; q < 2; ++q) {
        int idx = t + 256 * q;               // 0..511
        int g = row0 * DIM + idx;
        float z;
        if (first) {
            z = xin[g];
        } else {
            int row = row0 + (idx >> 6), j = idx & 63;
            float s = 0.f;
#pragma unroll
            for (int cbk = 0; cbk < 8; ++cbk)
                s += g_ypart[(row * 8 + cbk) * DIM + j];
            z = g_z[g] + dt * (s + b3[j]);
        }
        zs[idx] = z;
        g_z[g] = z;
    }
    __syncthreads();

    float acc0[8], acc1[8];
#pragma unroll
    for (int r = 0; r < 8; ++r) { acc0[r] = 0.f; acc1[r] = 0.f; }
    int c0 = t, c1 = t + 256;
#pragma unroll 4
    for (int k = 0; k < 64; ++k) {
        float wa = W1[k * HID + c0];
        float wb = W1[k * HID + c1];
#pragma unroll
        for (int r = 0; r < 8; ++r) {
            float z = zs[r * 64 + k];
            acc0[r] += z * wa;
            acc1[r] += z * wb;
        }
    }
    float ba = b1[c0], bb = b1[c1];
#pragma unroll
    for (int r = 0; r < 8; ++r) {
        g_h1[(row0 + r) * HID + c0] = fmaxf(acc0[r] + ba, 0.f);
        g_h1[(row0 + r) * HID + c1] = fmaxf(acc1[r] + bb, 0.f);
    }
}

// ---------------------------------------------------------------------------
// K2: over A = h1 [1024x512], tile 64x64, BK=16, grid (8,16):
//   u2    = h1 @ W2 + b2            (fp32 FFMA mainloop)
//   V     = (h1>0) @ Q              (bf16 wmma mainloop; fp32 accum)
//   ypart = relu(u2) @ W3[col0:+64] (fp32 epilogue, from smem)
//   partials: bilinear sum_i (u2>0)*V  and rowsum of ypart (no atomics).
// smem union: mainloop {ASM f32, BS1 f32, Am bf16, Qb bf16} -> Vbuf -> {H2S, W3S, RED}
// ---------------------------------------------------------------------------
#define ASM(k_, r_)  sm[(k_) * 64 + (r_)]
#define BS1(k_, c_)  sm[1024 + (k_) * 64 + (c_)]
#define VBUF(r_, c_) sm[(r_) * 68 + (c_)]
#define H2S(r_, c_)  sm[(r_) * 68 + (c_)]
#define W3S(k_, j_)  sm[4352 + (k_) * 68 + (j_)]
#define RED(x_, y_)  sm[8704 + (x_) * 64 + (y_)]

__global__ __launch_bounds__(256) void k2_layer2(const float* __restrict__ W2,
                                                 const float* __restrict__ b2,
                                                 const float* __restrict__ W3) {
    __shared__ float sm[8704 + 16 * 64];     // 38.9 KB
    __nv_bfloat16* Amb = (__nv_bfloat16*)(sm + 2048);   // mask tile [64 rows][16 k]
    __nv_bfloat16* Qbs = (__nv_bfloat16*)(sm + 2560);   // Q tile   [16 k][64 col]

    int cb = blockIdx.x;                 // 0..7
    int rb = blockIdx.y;                 // 0..15
    int row0 = rb * 64, col0 = cb * 64;
    int t = threadIdx.x;
    int tx = t & 15, ty = t >> 4;
    int warp = t >> 5;
    int rowblk = warp & 3, colgrp = warp >> 2;

    wmma::fragment<wmma::matrix_a, 16, 16, 16, __nv_bfloat16, wmma::row_major> fa;
    wmma::fragment<wmma::matrix_b, 16, 16, 16, __nv_bfloat16, wmma::row_major> fb;
    wmma::fragment<wmma::accumulator, 16, 16, 16, float> fc0, fc1;
    wmma::fill_fragment(fc0, 0.f);
    wmma::fill_fragment(fc1, 0.f);

    float au[4][4];
#pragma unroll
    for (int r = 0; r < 4; ++r)
#pragma unroll
        for (int c = 0; c < 4; ++c) au[r][c] = 0.f;

    int ar = t >> 2, ak = (t & 3) * 4;   // A load: row ar, k off ak
    int bk = t >> 4, bc = (t & 15) * 4;  // B loads: k row bk, col bc

    const __nv_bfloat16 bONE = __float2bfloat16(1.f);
    const __nv_bfloat16 bZERO = __float2bfloat16(0.f);

    for (int k0 = 0; k0 < HID; k0 += 16) {
        float4 a4 = *(const float4*)&g_h1[(row0 + ar) * HID + k0 + ak];
        ASM(ak + 0, ar) = a4.x; ASM(ak + 1, ar) = a4.y;
        ASM(ak + 2, ar) = a4.z; ASM(ak + 3, ar) = a4.w;
        // bf16 mask tile, row-major [ar][ak..ak+3]
        *(__nv_bfloat162*)&Amb[ar * 16 + ak] =
            __halves2bfloat162(a4.x > 0.f ? bONE : bZERO, a4.y > 0.f ? bONE : bZERO);
        *(__nv_bfloat162*)&Amb[ar * 16 + ak + 2] =
            __halves2bfloat162(a4.z > 0.f ? bONE : bZERO, a4.w > 0.f ? bONE : bZERO);
        *(float4*)&BS1(bk, bc) = *(const float4*)&W2[(k0 + bk) * HID + col0 + bc];
        *(uint2*)&Qbs[bk * 64 + bc] = *(const uint2*)&g_Qb[(k0 + bk) * HID + col0 + bc];
        __syncthreads();

        // fp32 u2 GEMM
#pragma unroll
        for (int kk = 0; kk < 16; ++kk) {
            float a[4], w[4];
            *(float4*)a = *(const float4*)&ASM(kk, ty * 4);
            *(float4*)w = *(const float4*)&BS1(kk, tx * 4);
#pragma unroll
            for (int r = 0; r < 4; ++r)
#pragma unroll
                for (int c = 0; c < 4; ++c) au[r][c] += a[r] * w[c];
        }
        // bf16 V GEMM (tensor core): warp covers rows rowblk*16, cols colgrp*32
        wmma::load_matrix_sync(fa, Amb + rowblk * 16 * 16, 16);
        wmma::load_matrix_sync(fb, Qbs + colgrp * 32, 64);
        wmma::mma_sync(fc0, fa, fb, fc0);
        wmma::load_matrix_sync(fb, Qbs + colgrp * 32 + 16, 64);
        wmma::mma_sync(fc1, fa, fb, fc1);
        __syncthreads();
    }

    // V fragments -> smem (overlaps dead mainloop buffers), then to regs
    wmma::store_matrix_sync(&VBUF(rowblk * 16, colgrp * 32),      fc0, 68, wmma::mem_row_major);
    wmma::store_matrix_sync(&VBUF(rowblk * 16, colgrp * 32 + 16), fc1, 68, wmma::mem_row_major);
    __syncthreads();
    float av[4][4];
#pragma unroll
    for (int r = 0; r < 4; ++r)
#pragma unroll
        for (int c = 0; c < 4; ++c) av[r][c] = VBUF(ty * 4 + r, tx * 4 + c);
    __syncthreads();

    // ---- epilogue phase 1: h2 tile -> smem, bilinear partial -> RED, W3 tile
    float b2v[4];
    *(float4*)b2v = *(const float4*)&b2[col0 + tx * 4];
#pragma unroll
    for (int r = 0; r < 4; ++r) {
        float h2v[4];
        float s = 0.f;
#pragma unroll
        for (int c = 0; c < 4; ++c) {
            float u = au[r][c] + b2v[c];
            h2v[c] = fmaxf(u, 0.f);
            s += (u > 0.f) ? av[r][c] : 0.f;
        }
        *(float4*)&H2S(ty * 4 + r, tx * 4) = *(float4*)h2v;
        RED(tx, ty * 4 + r) = s;
    }
#pragma unroll
    for (int q = 0; q < 4; ++q) {
        int f = t + 256 * q;              // float4 index 0..1023
        int k = f >> 4, j4 = (f & 15) * 4;
        *(float4*)&W3S(k, j4) = *(const float4*)&W3[(col0 + k) * DIM + j4];
    }
    __syncthreads();

    // ---- epilogue phase 2: ypart = h2_tile @ W3_tile
    float ay[4][4];
#pragma unroll
    for (int r = 0; r < 4; ++r)
#pragma unroll
        for (int c = 0; c < 4; ++c) ay[r][c] = 0.f;

#pragma unroll 8
    for (int k = 0; k < 64; ++k) {
        float a[4], w[4];
#pragma unroll
        for (int r = 0; r < 4; ++r) a[r] = H2S(ty * 4 + r, k);
        *(float4*)w = *(const float4*)&W3S(k, tx * 4);
#pragma unroll
        for (int r = 0; r < 4; ++r)
#pragma unroll
            for (int c = 0; c < 4; ++c) ay[r][c] += a[r] * w[c];
    }
#pragma unroll
    for (int r = 0; r < 4; ++r) {
        int row = row0 + ty * 4 + r;
        *(float4*)&g_ypart[(row * 8 + cb) * DIM + tx * 4] = *(float4*)ay[r];
    }

    // bilinear partial reduction (RED from phase 1)
    if (t < 64) {
        float s = 0.f;
#pragma unroll
        for (int x = 0; x < 16; ++x) s += RED(x, t);
        g_part[(row0 + t) * 8 + cb] = s;
    }
    __syncthreads();

    // rowsum-of-y partials (reuse RED)
#pragma unroll
    for (int r = 0; r < 4; ++r)
        RED(tx, ty * 4 + r) = ay[r][0] + ay[r][1] + ay[r][2] + ay[r][3];
    __syncthreads();
    if (t < 64) {
        float s = 0.f;
#pragma unroll
        for (int x = 0; x < 16; ++x) s += RED(x, t);
        g_ysump[(row0 + t) * 8 + cb] = s;
    }
}

// ---------------------------------------------------------------------------
// K3t (tiny): per row: Sy = sum_cb ysump; bilin = sum_cb part;
//   trace = (Sy - Sy_old)*dt/H + bilin*dt;  logdet -= trace;  store Sy.
// grid: 4 blocks * 256 threads.
// ---------------------------------------------------------------------------
__global__ __launch_bounds__(256) void k3_tiny(float* __restrict__ out_logdet,
                                               float dt, int newIdx, int dolog) {
    int row = blockIdx.x * 256 + threadIdx.x;
    float sy = 0.f, bl = 0.f;
#pragma unroll
    for (int cbk = 0; cbk < 8; ++cbk) {
        sy += g_ysump[row * 8 + cbk];
        bl += g_part [row * 8 + cbk];
    }
    if (dolog) {
        float trace = (sy - g_ysum[newIdx ^ 1][row]) * (dt / HSTEP) + bl * dt;
        out_logdet[row] -= trace;
    }
    g_ysum[newIdx][row] = sy;
}

// final z copy into d_out
__global__ __launch_bounds__(256) void k_final(float* __restrict__ out) {
    int i = blockIdx.x * 256 + threadIdx.x;
    out[i] = g_z[i];
}

// ---------------------------------------------------------------------------
extern "C" void kernel_launch(void* const* d_in, const int* in_sizes, int n_in,
                              void* d_out, int out_size) {
    (void)in_sizes; (void)n_in; (void)out_size;
    const float* x  = (const float*)d_in[0];
    const float* W1 = (const float*)d_in[1];
    const float* b1 = (const float*)d_in[2];
    const float* W2 = (const float*)d_in[3];
    const float* b2 = (const float*)d_in[4];
    const float* W3 = (const float*)d_in[5];
    const float* b3 = (const float*)d_in[6];
    float* out        = (float*)d_out;
    float* out_logdet = out + BATCH * DIM;

    float tt[NSTEP + 1];
    for (int i = 0; i <= NSTEP; ++i) tt[i] = (float)i / 9.0f;

    dim3 g2(8, 16);
    dim3 gi(8, 8);

    k_init<<<gi, 256>>>(W1, W2, W3, out_logdet);

    // eval 0 at z = x (fills g_z, ypart, Sy0; no log_det update)
    k1_layer1<<<128, 256>>>(x, W1, b1, b3, 0.f, 1);
    k2_layer2<<<g2, 256>>>(W2, b2, W3);
    k3_tiny<<<4, 256>>>(out_logdet, 0.f, 0, 0);

    // 9 Euler steps
    for (int s = 1; s <= NSTEP; ++s) {
        float dt = tt[s] - tt[s - 1];
        int newIdx = s & 1;
        k1_layer1<<<128, 256>>>(x, W1, b1, b3, dt, 0);   // z += dt*y_old; layer1
        k2_layer2<<<g2, 256>>>(W2, b2, W3);              // u2 fp32 + V bf16 + ypart
        k3_tiny<<<4, 256>>>(out_logdet, dt, newIdx, 1);
    }

    k_final<<<256, 256>>>(out);
}